// round 7
// baseline (speedup 1.0000x reference)
#include <cuda_runtime.h>
#include <math.h>

// CustomLoss: Voronoi phase -> 32x32 FFT2 magnitude vs Gaussian-mixture target,
// global-normalized scalar loss. GRID=16, PAD=32, RADIUS=8, SIGMA=1.5, NS=24, B=8192.
//
// R7: register-radix column FFT (8 lanes x 4 points -> 24 SHFL vs 40),
// natural-order sG[p][q] layout with stride-36 padding (conflict-free stores AND
// strided reads), -i swap-trick stages, launch_bounds(256,7).

#define NS 24
#define NT 256

__device__ double   g_sumP2 = 0.0;
__device__ double   g_sumT2 = 0.0;
__device__ double   g_sumPT = 0.0;
__device__ int      g_maxQ  = 0;   // float bits of max(P^2) (non-negative)
__device__ int      g_maxT  = 0;   // float bits of max(T)
__device__ unsigned g_count = 0;

__global__ void __launch_bounds__(NT, 7) loss_main(
    const float* __restrict__ output,
    const float* __restrict__ targets,
    float* __restrict__ out)
{
    __shared__ __align__(16) float4 sSeed[NS];    // (-2sx, -2sy, sx^2+sy^2+512, 0)
    __shared__ float2 sCS[NS];                    // (cos 2pi z, sin 2pi z) per seed
    __shared__ __align__(16) float sEx[NS][32];   // amp * exp(-(c - tx)^2 / 4.5)
    __shared__ __align__(16) float sEy[NS][32];   // exp(-(r - ty)^2 / 4.5)
    __shared__ float2 sTw[32];                    // W_32^k = exp(-2*pi*i*k/32)
    __shared__ float  sGr[32][36];                // row-FFT out (re): [spatial row][storage col]
    __shared__ float  sGi[32][36];                // row-FFT out (im)
    __shared__ double redD[24];
    __shared__ float  redF[16];

    const int tid  = threadIdx.x;
    const int w    = tid >> 5;
    const int lane = tid & 31;
    const int b    = blockIdx.x;
    const float* op = output  + b * (NS * 3);
    const float* tp = targets + b * (NS * 3);

    // ---- seeds (packed linear form) + per-seed phase cos/sin ----
    if (tid < NS) {
        float sx = op[3 * tid + 0];
        float sy = op[3 * tid + 1];
        float z  = op[3 * tid + 2];
        sSeed[tid] = make_float4(-2.0f * sx, -2.0f * sy,
                                 fmaf(sx, sx, fmaf(sy, sy, 512.0f)), 0.0f);
        float s, c;
        sincospif(2.0f * z, &s, &c);
        sCS[tid] = make_float2(c, s);
    }
    // ---- twiddle table ----
    if (tid >= 32 && tid < 64) {
        int k = tid - 32;
        float s, c;
        sincospif(-(float)k * (1.0f / 16.0f), &s, &c);
        sTw[k] = make_float2(c, s);
    }
    // ---- separable Gaussian factors for the target ----
    for (int t = tid; t < NS * 32; t += NT) {
        int s = t >> 5, x = t & 31;
        float tx  = tp[3 * s + 0];
        float ty  = tp[3 * s + 1];
        float amp = tp[3 * s + 2];
        float dx = (float)x - tx;
        float dy = (float)x - ty;
        sEx[s][x] = amp * expf(dx * dx * (-1.0f / 4.5f));
        sEy[s][x] = expf(dy * dy * (-1.0f / 4.5f));
    }
    __syncthreads();

    // ---- row-pass per-lane twiddles (stages h=16,8,4; h=2 is swap-trick, h=1 identity) ----
    float twr[3], twi[3];
    #pragma unroll
    for (int st = 0; st < 3; st++) {
        int h = 16 >> st;
        int idx = (lane & h) ? ((lane & (h - 1)) << st) : 0;
        float2 tw = sTw[idx];
        twr[st] = tw.x; twi[st] = tw.y;
    }

    // ============ DENSITY for rows 8..23 (m=1: p=w+8, m=2: p=w+16) ============
    float rr[2], ri[2];
    {
        const int   rq  = lane - 16;
        const int   rq2 = rq * rq;
        const float fj  = (float)(lane - 8);
        const float fi1 = (float)w;
        int best1 = 0x7fffffff, best2 = 0x7fffffff;
        #pragma unroll
        for (int s = 0; s < NS; s++) {
            float4 S = sSeed[s];
            float t0   = fmaf(fj, S.y, S.z);
            float val1 = fmaf(fi1, S.x, t0);
            float val2 = fmaf(8.0f, S.x, val1);
            int k1 = (__float_as_int(val1) & 0xffffffe0) | s;
            int k2 = (__float_as_int(val2) & 0xffffffe0) | s;
            best1 = min(best1, k1);
            best2 = min(best2, k2);
        }
        int lbl1 = (lane < 24) ? (best1 & 31) : 0;
        int lbl2 = (lane < 24) ? (best2 & 31) : 0;
        float2 cs1 = sCS[lbl1];
        float2 cs2 = sCS[lbl2];
        {   // p = w+8 : rp = w-8
            int rp = w - 8;
            bool in = (rp * rp + rq2 <= 64);
            rr[0] = in ? cs1.x : 1.0f;
            ri[0] = in ? cs1.y : 0.0f;
        }
        {   // p = w+16 : rp = w
            bool in = (w * w + rq2 <= 64);
            rr[1] = in ? cs2.x : 1.0f;
            ri[1] = in ? cs2.y : 0.0f;
        }
    }

    // ---- analytic row FFTs for rows 0..7 and 24..31 ----
    // Storage col q holds freq brev5(q). All-ones row: 32 at freq 0 (q=0).
    // Row 24 extra term (cell q=16, label 0): (cs0-1)*(-1)^freq; parity(brev(q)) = q>>4.
    {
        float dc = (lane == 0) ? 32.0f : 0.0f;
        sGr[w][lane] = dc;            // rows 0..7
        sGi[w][lane] = 0.0f;
        if (w == 0) {
            float2 cs0 = sCS[0];
            float sg = (lane & 16) ? -1.0f : 1.0f;
            sGr[24][lane] = dc + (cs0.x - 1.0f) * sg;
            sGi[24][lane] = cs0.y * sg;
        } else {
            sGr[24 + w][lane] = dc;   // rows 25..31
            sGi[24 + w][lane] = 0.0f;
        }
    }

    // ============ ROW FFT (rows 8..23; lane = spatial col) ============
    #pragma unroll
    for (int st = 0; st < 3; st++) {
        int h = 16 >> st;
        float sg = (lane & h) ? -1.0f : 1.0f;
        float wr = twr[st], wi = twi[st];
        #pragma unroll
        for (int m = 0; m < 2; m++) {
            float o_r = __shfl_xor_sync(0xffffffffu, rr[m], h);
            float o_i = __shfl_xor_sync(0xffffffffu, ri[m], h);
            float ur = fmaf(sg, rr[m], o_r);
            float ui = fmaf(sg, ri[m], o_i);
            rr[m] = fmaf(ur, wr, -ui * wi);
            ri[m] = fmaf(ur, wi,  ui * wr);
        }
    }
    {   // stage h=2: twiddle (-i)^(lane&1) on lanes with (lane&2) -> swap trick
        float sg = (lane & 2) ? -1.0f : 1.0f;
        bool  sw = (lane & 3) == 3;
        #pragma unroll
        for (int m = 0; m < 2; m++) {
            float o_r = __shfl_xor_sync(0xffffffffu, rr[m], 2);
            float o_i = __shfl_xor_sync(0xffffffffu, ri[m], 2);
            float ur = fmaf(sg, rr[m], o_r);
            float ui = fmaf(sg, ri[m], o_i);
            rr[m] = sw ?  ui : ur;
            ri[m] = sw ? -ur : ui;
        }
    }
    {   // stage h=1: identity twiddles
        float sg = (lane & 1) ? -1.0f : 1.0f;
        #pragma unroll
        for (int m = 0; m < 2; m++) {
            float o_r = __shfl_xor_sync(0xffffffffu, rr[m], 1);
            float o_i = __shfl_xor_sync(0xffffffffu, ri[m], 1);
            rr[m] = fmaf(sg, rr[m], o_r);
            ri[m] = fmaf(sg, ri[m], o_i);
        }
    }

    // store natural order: storage col = lane (freq brev(lane)); banks = lane -> conflict-free
    sGr[w + 8][lane]  = rr[0];
    sGi[w + 8][lane]  = ri[0];
    sGr[w + 16][lane] = rr[1];
    sGi[w + 16][lane] = ri[1];
    __syncthreads();

    // ============ COLUMN FFT: 8 lanes/column, 4 points/thread ============
    // Storage column sc = 4w + (lane>>3); thread holds rows p = (lane&7) + 8m.
    const int l7 = lane & 7;
    const int sc = (w << 2) + (lane >> 3);
    float2 W1 = sTw[l7];            // W^{l7}
    float2 W2 = sTw[l7 << 1];       // W^{2*l7}
    float2 W4 = sTw[(lane & 4) ? ((lane & 3) << 2) : 0];

    float cr[4], ci[4];
    #pragma unroll
    for (int m = 0; m < 4; m++) {
        int p = l7 + (m << 3);
        cr[m] = sGr[p][sc];         // addr = 36p + sc: banks 4*(l7)+(lane>>3) all distinct
        ci[m] = sGi[p][sc];
    }
    // stage h=16 (register): pairs (m, m+2); v0 *= W^{l7}, v1 *= W^{l7+8} = W^{l7} * (-i)
    {
        float t0r = cr[0] - cr[2], t0i = ci[0] - ci[2];
        float t1r = cr[1] - cr[3], t1i = ci[1] - ci[3];
        cr[0] += cr[2]; ci[0] += ci[2];
        cr[1] += cr[3]; ci[1] += ci[3];
        cr[2] = fmaf(t0r, W1.x, -t0i * W1.y);
        ci[2] = fmaf(t0r, W1.y,  t0i * W1.x);
        float p1r = fmaf(t1r, W1.x, -t1i * W1.y);
        float p1i = fmaf(t1r, W1.y,  t1i * W1.x);
        cr[3] =  p1i;               // * (-i)
        ci[3] = -p1r;
    }
    // stage h=8 (register): pairs (0,1),(2,3) with W^{2*l7}
    {
        float tr = cr[0] - cr[1], ti = ci[0] - ci[1];
        cr[0] += cr[1]; ci[0] += ci[1];
        cr[1] = fmaf(tr, W2.x, -ti * W2.y);
        ci[1] = fmaf(tr, W2.y,  ti * W2.x);
        float sr = cr[2] - cr[3], si = ci[2] - ci[3];
        cr[2] += cr[3]; ci[2] += ci[3];
        cr[3] = fmaf(sr, W2.x, -si * W2.y);
        ci[3] = fmaf(sr, W2.y,  si * W2.x);
    }
    // stage h=4 (shuffle xor 4): twiddle W^{4*(l7&3)} on upper lanes
    {
        float sg = (lane & 4) ? -1.0f : 1.0f;
        #pragma unroll
        for (int m = 0; m < 4; m++) {
            float o_r = __shfl_xor_sync(0xffffffffu, cr[m], 4);
            float o_i = __shfl_xor_sync(0xffffffffu, ci[m], 4);
            float ur = fmaf(sg, cr[m], o_r);
            float ui = fmaf(sg, ci[m], o_i);
            cr[m] = fmaf(ur, W4.x, -ui * W4.y);
            ci[m] = fmaf(ur, W4.y,  ui * W4.x);
        }
    }
    // stage h=2 (shuffle xor 2): twiddle (-i)^(l&1) on lanes with (l&2) -> swap trick
    {
        float sg = (lane & 2) ? -1.0f : 1.0f;
        bool  sw = (lane & 3) == 3;
        #pragma unroll
        for (int m = 0; m < 4; m++) {
            float o_r = __shfl_xor_sync(0xffffffffu, cr[m], 2);
            float o_i = __shfl_xor_sync(0xffffffffu, ci[m], 2);
            float ur = fmaf(sg, cr[m], o_r);
            float ui = fmaf(sg, ci[m], o_i);
            cr[m] = sw ?  ui : ur;
            ci[m] = sw ? -ur : ui;
        }
    }
    // stage h=1 (shuffle xor 1): identity
    {
        float sg = (lane & 1) ? -1.0f : 1.0f;
        #pragma unroll
        for (int m = 0; m < 4; m++) {
            float o_r = __shfl_xor_sync(0xffffffffu, cr[m], 1);
            float o_i = __shfl_xor_sync(0xffffffffu, ci[m], 1);
            cr[m] = fmaf(sg, cr[m], o_r);
            ci[m] = fmaf(sg, ci[m], o_i);
        }
    }

    // ---- magnitude + target + accumulate ----
    // Thread's value m sits at (freq k1_m, freq k2):
    //   k1_m = brev5(l7 + 8m) = rbase + perm(m), perm = [0,2,1,3]; k2 = brev5(sc).
    //   Shifted (r, c) = (k1_m ^ 16, k2 ^ 16); rbase^16 is 4-aligned -> ey float4.
    float aP2 = 0.0f, aT2 = 0.0f, aPT = 0.0f, mQ = 0.0f, mT = 0.0f;
    {
        int rbase = ((__brev(l7) >> 27) ^ 16);      // 4-aligned
        int c     = (__brev(sc) >> 27) ^ 16;
        float Q[4], P[4], T[4];
        #pragma unroll
        for (int m = 0; m < 4; m++) {
            Q[m] = fmaf(cr[m], cr[m], ci[m] * ci[m]);
            P[m] = sqrtf(Q[m]);
            T[m] = 0.0f;
        }
        #pragma unroll
        for (int s = 0; s < NS; s++) {
            float  ex = sEx[s][c];
            float4 E  = *reinterpret_cast<const float4*>(&sEy[s][rbase]);
            T[0] = fmaf(ex, E.x, T[0]);   // r offset 0
            T[1] = fmaf(ex, E.z, T[1]);   // r offset 2
            T[2] = fmaf(ex, E.y, T[2]);   // r offset 1
            T[3] = fmaf(ex, E.w, T[3]);   // r offset 3
        }
        #pragma unroll
        for (int m = 0; m < 4; m++) {
            aP2 += Q[m];
            aT2 = fmaf(T[m], T[m], aT2);
            aPT = fmaf(P[m], T[m], aPT);
            mQ = fmaxf(mQ, Q[m]);
            mT = fmaxf(mT, T[m]);
        }
    }

    // warp reduce
    #pragma unroll
    for (int off = 16; off; off >>= 1) {
        aP2 += __shfl_down_sync(0xffffffffu, aP2, off);
        aT2 += __shfl_down_sync(0xffffffffu, aT2, off);
        aPT += __shfl_down_sync(0xffffffffu, aPT, off);
        mQ = fmaxf(mQ, __shfl_down_sync(0xffffffffu, mQ, off));
        mT = fmaxf(mT, __shfl_down_sync(0xffffffffu, mT, off));
    }
    if (lane == 0) {
        redD[w]      = (double)aP2;
        redD[8 + w]  = (double)aT2;
        redD[16 + w] = (double)aPT;
        redF[w]      = mQ;
        redF[8 + w]  = mT;
    }
    __syncthreads();
    if (tid == 0) {
        double bP2 = 0.0, bT2 = 0.0, bPT = 0.0;
        float  bMQ = 0.0f, bMT = 0.0f;
        #pragma unroll
        for (int i = 0; i < 8; i++) {
            bP2 += redD[i];
            bT2 += redD[8 + i];
            bPT += redD[16 + i];
            bMQ = fmaxf(bMQ, redF[i]);
            bMT = fmaxf(bMT, redF[8 + i]);
        }
        atomicAdd(&g_sumP2, bP2);
        atomicAdd(&g_sumT2, bT2);
        atomicAdd(&g_sumPT, bPT);
        atomicMax(&g_maxQ, __float_as_int(bMQ));
        atomicMax(&g_maxT, __float_as_int(bMT));

        __threadfence();
        unsigned prev = atomicAdd(&g_count, 1u);
        if (prev == gridDim.x - 1u) {
            __threadfence();
            double SP2 = g_sumP2;
            double ST2 = g_sumT2;
            double SPT = g_sumPT;
            double Mp = sqrt((double)__int_as_float(g_maxQ));
            double Mt = (double)__int_as_float(g_maxT);
            double num = SP2 / (Mp * Mp) - 2.0 * SPT / (Mp * Mt) + ST2 / (Mt * Mt);
            out[0] = (float)(num * (Mp * Mt) / sqrt(SP2 * ST2));
            // self-reset for next graph replay (matches static init state)
            g_sumP2 = 0.0;
            g_sumT2 = 0.0;
            g_sumPT = 0.0;
            g_maxQ  = 0;
            g_maxT  = 0;
            g_count = 0u;
        }
    }
}

extern "C" void kernel_launch(void* const* d_in, const int* in_sizes, int n_in,
                              void* d_out, int out_size)
{
    const float* output  = (const float*)d_in[0];
    const float* targets = (const float*)d_in[1];
    int B = in_sizes[0] / (NS * 3);

    loss_main<<<B, NT>>>(output, targets, (float*)d_out);
}

// round 8
// speedup vs baseline: 1.0552x; 1.0552x over previous
#include <cuda_runtime.h>
#include <math.h>

// CustomLoss: Voronoi phase -> 32x32 FFT2 magnitude vs Gaussian-mixture target,
// global-normalized scalar loss. GRID=16, PAD=32, RADIUS=8, SIGMA=1.5, NS=24, B=8192.
//
// R8: 2 batches/block (shared reduction+atomics), single-argmin Voronoi via
// column-pair row tiling, register-radix row FFT (16 SHFL), redux.sync maxes.

#define NS 24
#define NT 256
#define NB 2

__device__ double   g_sumP2 = 0.0;
__device__ double   g_sumT2 = 0.0;
__device__ double   g_sumPT = 0.0;
__device__ int      g_maxQ  = 0;   // float bits of max(P^2) (non-negative)
__device__ int      g_maxT  = 0;   // float bits of max(T)
__device__ unsigned g_count = 0;

__global__ void __launch_bounds__(NT, 6) loss_main(
    const float* __restrict__ output,
    const float* __restrict__ targets,
    float* __restrict__ out)
{
    __shared__ __align__(16) float4 sSeed[NS];    // (-2sx, -2sy, sx^2+sy^2+512, 0)
    __shared__ float2 sCS[NS];                    // (cos 2pi z, sin 2pi z) per seed
    __shared__ __align__(16) float sEx[NS][32];   // amp * exp(-(c - tx)^2 / 4.5)
    __shared__ __align__(16) float sEy[NS][32];   // exp(-(r - ty)^2 / 4.5)
    __shared__ float2 sTw[32];                    // W_32^k = exp(-2*pi*i*k/32)
    __shared__ float  sGr[32][36];                // row-FFT out (re): [spatial row][storage col]
    __shared__ float  sGi[32][36];                // row-FFT out (im)
    __shared__ double redD[24];

    const int tid  = threadIdx.x;
    const int w    = tid >> 5;
    const int lane = tid & 31;

    // ---- twiddle table (once) ----
    if (tid >= 32 && tid < 64) {
        int k = tid - 32;
        float s, c;
        sincospif(-(float)k * (1.0f / 16.0f), &s, &c);
        sTw[k] = make_float2(c, s);
    }
    __syncthreads();

    // ---- hoisted per-lane twiddles ----
    // Row pass (16-lane FFTs after register stage): W_16 = W_32^2.
    const int colA = lane & 15;                   // column in [0,16) handled by this thread
    float2 Wrow = sTw[colA];                                        // register-stage twiddle W_32^colA
    float2 T8   = (lane & 8) ? sTw[(lane & 7) << 1] : make_float2(1.0f, 0.0f);
    float2 T4r  = (lane & 4) ? sTw[(lane & 3) << 2] : make_float2(1.0f, 0.0f);
    // Col pass (8 lanes x 4 points): register stages h=16,8 then shuffles h=4,2,1.
    const int l7 = lane & 7;
    const int sc = (w << 2) + (lane >> 3);        // storage column
    float2 W1 = sTw[l7];
    float2 W2 = sTw[l7 << 1];
    float2 W4 = (lane & 4) ? sTw[(lane & 3) << 2] : make_float2(1.0f, 0.0f);

    // Row-pass tiling: row = 8 + (w&3) + 8*(w>>2) + 4*(lane>>4)  (covers rows 8..23;
    // row-pair delta 4 keeps stride-36 stores conflict-free).
    const int  row = 8 + (w & 3) + ((w >> 2) << 3) + ((lane >> 4) << 2);
    const int  rp  = row - 16;
    const int  rp2 = rp * rp;
    const float fi = (float)(row - 8);
    // The single Voronoi cell this thread can own: j = colA-8 (if colA>=8) else colA+8.
    const float fj = (float)((lane & 8) ? (lane & 7) : ((lane & 7) + 8));

    // Output mapping (constant per thread):
    //   col-FFT value m lives at k1_m = rbase' + perm[m], perm=[0,2,1,3]; r = k1^16.
    //   k2(sc) = 2*brev4(sc&15) + (sc>>4); c = k2^16.
    const int rbase = ((__brev(l7) >> 27) ^ 16);  // 4-aligned
    const int c     = ((((__brev(sc & 15) >> 28)) << 1) + (sc >> 4)) ^ 16;

    const int b = blockIdx.x;

    float aP2 = 0.0f, aT2 = 0.0f, aPT = 0.0f, mQ = 0.0f, mT = 0.0f;

    for (int nb = 0; nb < NB; nb++) {
        const int batch = b * NB + nb;
        const float* op = output  + batch * (NS * 3);
        const float* tp = targets + batch * (NS * 3);

        // ---- fills ----
        if (tid < NS) {
            float sx = op[3 * tid + 0];
            float sy = op[3 * tid + 1];
            float z  = op[3 * tid + 2];
            sSeed[tid] = make_float4(-2.0f * sx, -2.0f * sy,
                                     fmaf(sx, sx, fmaf(sy, sy, 512.0f)), 0.0f);
            float s, cz;
            sincospif(2.0f * z, &s, &cz);
            sCS[tid] = make_float2(cz, s);
        }
        for (int t = tid; t < NS * 32; t += NT) {
            int s = t >> 5, x = t & 31;
            float tx  = tp[3 * s + 0];
            float ty  = tp[3 * s + 1];
            float amp = tp[3 * s + 2];
            float dx = (float)x - tx;
            float dy = (float)x - ty;
            sEx[s][x] = amp * expf(dx * dx * (-1.0f / 4.5f));
            sEy[s][x] = expf(dy * dy * (-1.0f / 4.5f));
        }
        __syncthreads();

        // ---- single Voronoi argmin for this thread's ownable cell ----
        int best = 0x7fffffff;
        #pragma unroll
        for (int s = 0; s < NS; s++) {
            float4 S = sSeed[s];
            float val = fmaf(fi, S.x, fmaf(fj, S.y, S.z));
            best = min(best, (__float_as_int(val) & 0xffffffe0) | s);
        }
        const int L = best & 31;

        // ---- density for cells (row, colA) and (row, colA+16) ----
        // cellA inside disk  => colA in [8,15] => label = L.
        // cellB inside disk  => colA in [0,8]; label = L if colA<=7 else 0.
        float xAr, xAi, xBr, xBi;
        {
            int dA = colA - 16;
            bool inA = (rp2 + dA * dA <= 64);
            float2 csA = sCS[L];
            xAr = inA ? csA.x : 1.0f;
            xAi = inA ? csA.y : 0.0f;

            bool inB = (rp2 + colA * colA <= 64);
            int lblB = (colA <= 7) ? L : 0;
            float2 csB = sCS[lblB];
            xBr = inB ? csB.x : 1.0f;
            xBi = inB ? csB.y : 0.0f;
        }

        // ---- analytic row FFTs for rows 0..7 and 24..31 ----
        // storage col sc' holds freq k2(sc'); k2=0 <=> sc'=0; parity(k2) = sc'>>4.
        {
            float dc = (lane == 0) ? 32.0f : 0.0f;
            sGr[w][lane] = dc;            // rows 0..7
            sGi[w][lane] = 0.0f;
            if (w == 0) {
                float2 cs0 = sCS[0];
                float sg = (lane & 16) ? -1.0f : 1.0f;
                sGr[24][lane] = dc + (cs0.x - 1.0f) * sg;
                sGi[24][lane] = cs0.y * sg;
            } else {
                sGr[24 + w][lane] = dc;   // rows 25..31
                sGi[24 + w][lane] = 0.0f;
            }
        }

        // ---- ROW FFT: register stage h=16, then 4 shuffle stages in 16-lane groups ----
        float ar = xAr + xBr, ai = xAi + xBi;
        float tr = xAr - xBr, ti = xAi - xBi;
        float br = fmaf(tr, Wrow.x, -ti * Wrow.y);
        float bi = fmaf(tr, Wrow.y,  ti * Wrow.x);

        {   // h=8, twiddle T8
            float sg = (lane & 8) ? -1.0f : 1.0f;
            float oar = __shfl_xor_sync(0xffffffffu, ar, 8);
            float oai = __shfl_xor_sync(0xffffffffu, ai, 8);
            float obr = __shfl_xor_sync(0xffffffffu, br, 8);
            float obi = __shfl_xor_sync(0xffffffffu, bi, 8);
            float uar = fmaf(sg, ar, oar), uai = fmaf(sg, ai, oai);
            float ubr = fmaf(sg, br, obr), ubi = fmaf(sg, bi, obi);
            ar = fmaf(uar, T8.x, -uai * T8.y); ai = fmaf(uar, T8.y, uai * T8.x);
            br = fmaf(ubr, T8.x, -ubi * T8.y); bi = fmaf(ubr, T8.y, ubi * T8.x);
        }
        {   // h=4, twiddle T4r
            float sg = (lane & 4) ? -1.0f : 1.0f;
            float oar = __shfl_xor_sync(0xffffffffu, ar, 4);
            float oai = __shfl_xor_sync(0xffffffffu, ai, 4);
            float obr = __shfl_xor_sync(0xffffffffu, br, 4);
            float obi = __shfl_xor_sync(0xffffffffu, bi, 4);
            float uar = fmaf(sg, ar, oar), uai = fmaf(sg, ai, oai);
            float ubr = fmaf(sg, br, obr), ubi = fmaf(sg, bi, obi);
            ar = fmaf(uar, T4r.x, -uai * T4r.y); ai = fmaf(uar, T4r.y, uai * T4r.x);
            br = fmaf(ubr, T4r.x, -ubi * T4r.y); bi = fmaf(ubr, T4r.y, ubi * T4r.x);
        }
        {   // h=2, twiddle (-i)^(lane&1) -> swap trick
            float sg = (lane & 2) ? -1.0f : 1.0f;
            bool  sw = (lane & 3) == 3;
            float oar = __shfl_xor_sync(0xffffffffu, ar, 2);
            float oai = __shfl_xor_sync(0xffffffffu, ai, 2);
            float obr = __shfl_xor_sync(0xffffffffu, br, 2);
            float obi = __shfl_xor_sync(0xffffffffu, bi, 2);
            float uar = fmaf(sg, ar, oar), uai = fmaf(sg, ai, oai);
            float ubr = fmaf(sg, br, obr), ubi = fmaf(sg, bi, obi);
            ar = sw ?  uai : uar;  ai = sw ? -uar : uai;
            br = sw ?  ubi : ubr;  bi = sw ? -ubr : ubi;
        }
        {   // h=1, identity
            float sg = (lane & 1) ? -1.0f : 1.0f;
            float oar = __shfl_xor_sync(0xffffffffu, ar, 1);
            float oai = __shfl_xor_sync(0xffffffffu, ai, 1);
            float obr = __shfl_xor_sync(0xffffffffu, br, 1);
            float obi = __shfl_xor_sync(0xffffffffu, bi, 1);
            ar = fmaf(sg, ar, oar); ai = fmaf(sg, ai, oai);
            br = fmaf(sg, br, obr); bi = fmaf(sg, bi, obi);
        }

        // store: a (even freqs) -> col colA, b (odd freqs) -> col colA+16; conflict-free
        sGr[row][colA]      = ar;
        sGi[row][colA]      = ai;
        sGr[row][colA + 16] = br;
        sGi[row][colA + 16] = bi;
        __syncthreads();

        // ---- COLUMN FFT: 8 lanes/column, 4 points/thread ----
        float cr[4], ci[4];
        #pragma unroll
        for (int m = 0; m < 4; m++) {
            int p = l7 + (m << 3);
            cr[m] = sGr[p][sc];
            ci[m] = sGi[p][sc];
        }
        {   // h=16 (register): v0 *= W^{l7}, v1 *= W^{l7+8} = W^{l7}*(-i)
            float t0r = cr[0] - cr[2], t0i = ci[0] - ci[2];
            float t1r = cr[1] - cr[3], t1i = ci[1] - ci[3];
            cr[0] += cr[2]; ci[0] += ci[2];
            cr[1] += cr[3]; ci[1] += ci[3];
            cr[2] = fmaf(t0r, W1.x, -t0i * W1.y);
            ci[2] = fmaf(t0r, W1.y,  t0i * W1.x);
            float p1r = fmaf(t1r, W1.x, -t1i * W1.y);
            float p1i = fmaf(t1r, W1.y,  t1i * W1.x);
            cr[3] =  p1i;
            ci[3] = -p1r;
        }
        {   // h=8 (register) with W^{2*l7}
            float t0r = cr[0] - cr[1], t0i = ci[0] - ci[1];
            cr[0] += cr[1]; ci[0] += ci[1];
            cr[1] = fmaf(t0r, W2.x, -t0i * W2.y);
            ci[1] = fmaf(t0r, W2.y,  t0i * W2.x);
            float t1r = cr[2] - cr[3], t1i = ci[2] - ci[3];
            cr[2] += cr[3]; ci[2] += ci[3];
            cr[3] = fmaf(t1r, W2.x, -t1i * W2.y);
            ci[3] = fmaf(t1r, W2.y,  t1i * W2.x);
        }
        {   // h=4 (shuffle) with W4
            float sg = (lane & 4) ? -1.0f : 1.0f;
            #pragma unroll
            for (int m = 0; m < 4; m++) {
                float o_r = __shfl_xor_sync(0xffffffffu, cr[m], 4);
                float o_i = __shfl_xor_sync(0xffffffffu, ci[m], 4);
                float ur = fmaf(sg, cr[m], o_r);
                float ui = fmaf(sg, ci[m], o_i);
                cr[m] = fmaf(ur, W4.x, -ui * W4.y);
                ci[m] = fmaf(ur, W4.y,  ui * W4.x);
            }
        }
        {   // h=2 swap trick
            float sg = (lane & 2) ? -1.0f : 1.0f;
            bool  sw = (lane & 3) == 3;
            #pragma unroll
            for (int m = 0; m < 4; m++) {
                float o_r = __shfl_xor_sync(0xffffffffu, cr[m], 2);
                float o_i = __shfl_xor_sync(0xffffffffu, ci[m], 2);
                float ur = fmaf(sg, cr[m], o_r);
                float ui = fmaf(sg, ci[m], o_i);
                cr[m] = sw ?  ui : ur;
                ci[m] = sw ? -ur : ui;
            }
        }
        {   // h=1 identity
            float sg = (lane & 1) ? -1.0f : 1.0f;
            #pragma unroll
            for (int m = 0; m < 4; m++) {
                float o_r = __shfl_xor_sync(0xffffffffu, cr[m], 1);
                float o_i = __shfl_xor_sync(0xffffffffu, ci[m], 1);
                cr[m] = fmaf(sg, cr[m], o_r);
                ci[m] = fmaf(sg, ci[m], o_i);
            }
        }

        // ---- magnitude + target + accumulate (into cross-batch registers) ----
        {
            float Q[4], P[4], T[4];
            #pragma unroll
            for (int m = 0; m < 4; m++) {
                Q[m] = fmaf(cr[m], cr[m], ci[m] * ci[m]);
                P[m] = sqrtf(Q[m]);
                T[m] = 0.0f;
            }
            #pragma unroll
            for (int s = 0; s < NS; s++) {
                float  ex = sEx[s][c];
                float4 E  = *reinterpret_cast<const float4*>(&sEy[s][rbase]);
                T[0] = fmaf(ex, E.x, T[0]);   // r offset 0
                T[1] = fmaf(ex, E.z, T[1]);   // r offset 2
                T[2] = fmaf(ex, E.y, T[2]);   // r offset 1
                T[3] = fmaf(ex, E.w, T[3]);   // r offset 3
            }
            #pragma unroll
            for (int m = 0; m < 4; m++) {
                aP2 += Q[m];
                aT2 = fmaf(T[m], T[m], aT2);
                aPT = fmaf(P[m], T[m], aPT);
                mQ = fmaxf(mQ, Q[m]);
                mT = fmaxf(mT, T[m]);
            }
        }
        __syncthreads();   // before next batch overwrites smem
    }

    // ---- block reduction (once per NB batches) ----
    unsigned ruQ = __reduce_max_sync(0xffffffffu, (unsigned)__float_as_int(mQ));
    unsigned ruT = __reduce_max_sync(0xffffffffu, (unsigned)__float_as_int(mT));
    #pragma unroll
    for (int off = 16; off; off >>= 1) {
        aP2 += __shfl_down_sync(0xffffffffu, aP2, off);
        aT2 += __shfl_down_sync(0xffffffffu, aT2, off);
        aPT += __shfl_down_sync(0xffffffffu, aPT, off);
    }
    __shared__ int redI[16];
    if (lane == 0) {
        redD[w]      = (double)aP2;
        redD[8 + w]  = (double)aT2;
        redD[16 + w] = (double)aPT;
        redI[w]      = (int)ruQ;
        redI[8 + w]  = (int)ruT;
    }
    __syncthreads();
    if (tid == 0) {
        double bP2 = 0.0, bT2 = 0.0, bPT = 0.0;
        int    bMQ = 0, bMT = 0;
        #pragma unroll
        for (int i = 0; i < 8; i++) {
            bP2 += redD[i];
            bT2 += redD[8 + i];
            bPT += redD[16 + i];
            bMQ = max(bMQ, redI[i]);
            bMT = max(bMT, redI[8 + i]);
        }
        atomicAdd(&g_sumP2, bP2);
        atomicAdd(&g_sumT2, bT2);
        atomicAdd(&g_sumPT, bPT);
        atomicMax(&g_maxQ, bMQ);
        atomicMax(&g_maxT, bMT);

        __threadfence();
        unsigned prev = atomicAdd(&g_count, 1u);
        if (prev == gridDim.x - 1u) {
            __threadfence();
            double SP2 = g_sumP2;
            double ST2 = g_sumT2;
            double SPT = g_sumPT;
            double Mp = sqrt((double)__int_as_float(g_maxQ));
            double Mt = (double)__int_as_float(g_maxT);
            double num = SP2 / (Mp * Mp) - 2.0 * SPT / (Mp * Mt) + ST2 / (Mt * Mt);
            out[0] = (float)(num * (Mp * Mt) / sqrt(SP2 * ST2));
            // self-reset for next graph replay (matches static init state)
            g_sumP2 = 0.0;
            g_sumT2 = 0.0;
            g_sumPT = 0.0;
            g_maxQ  = 0;
            g_maxT  = 0;
            g_count = 0u;
        }
    }
}

extern "C" void kernel_launch(void* const* d_in, const int* in_sizes, int n_in,
                              void* d_out, int out_size)
{
    const float* output  = (const float*)d_in[0];
    const float* targets = (const float*)d_in[1];
    int B = in_sizes[0] / (NS * 3);

    loss_main<<<B / NB, NT>>>(output, targets, (float*)d_out);
}

// round 9
// speedup vs baseline: 1.0847x; 1.0279x over previous
#include <cuda_runtime.h>
#include <math.h>

// CustomLoss: Voronoi phase -> 32x32 FFT2 magnitude vs Gaussian-mixture target,
// global-normalized scalar loss. GRID=16, PAD=32, RADIUS=8, SIGMA=1.5, NS=24, B=8192.
//
// R9: __expf tables, float2-merged transpose buffer (STS.64/LDS.64),
// transposed ex table with LDS.64 pairs in the T-sum.

#define NS 24
#define NT 256
#define NB 2

__device__ double   g_sumP2 = 0.0;
__device__ double   g_sumT2 = 0.0;
__device__ double   g_sumPT = 0.0;
__device__ int      g_maxQ  = 0;   // float bits of max(P^2) (non-negative)
__device__ int      g_maxT  = 0;   // float bits of max(T)
__device__ unsigned g_count = 0;

__global__ void __launch_bounds__(NT, 6) loss_main(
    const float* __restrict__ output,
    const float* __restrict__ targets,
    float* __restrict__ out)
{
    __shared__ __align__(16) float4 sSeed[NS];    // (-2sx, -2sy, sx^2+sy^2+512, 0)
    __shared__ float2 sCS[NS];                    // (cos 2pi z, sin 2pi z) per seed
    __shared__ __align__(16) float sExT[32][26];  // TRANSPOSED: [c][s], stride 26
    __shared__ __align__(16) float sEy[NS][32];   // exp(-(r - ty)^2 / 4.5)
    __shared__ float2 sTw[32];                    // W_32^k = exp(-2*pi*i*k/32)
    __shared__ __align__(16) float2 sG[32][36];   // row-FFT out: [spatial row][storage col]
    __shared__ double redD[24];

    const int tid  = threadIdx.x;
    const int w    = tid >> 5;
    const int lane = tid & 31;

    // ---- twiddle table (once) ----
    if (tid >= 32 && tid < 64) {
        int k = tid - 32;
        float s, c;
        sincospif(-(float)k * (1.0f / 16.0f), &s, &c);
        sTw[k] = make_float2(c, s);
    }
    __syncthreads();

    // ---- hoisted per-lane twiddles ----
    const int colA = lane & 15;
    float2 Wrow = sTw[colA];
    float2 T8   = (lane & 8) ? sTw[(lane & 7) << 1] : make_float2(1.0f, 0.0f);
    float2 T4r  = (lane & 4) ? sTw[(lane & 3) << 2] : make_float2(1.0f, 0.0f);
    const int l7 = lane & 7;
    const int sc = (w << 2) + (lane >> 3);
    float2 W1 = sTw[l7];
    float2 W2 = sTw[l7 << 1];
    float2 W4 = (lane & 4) ? sTw[(lane & 3) << 2] : make_float2(1.0f, 0.0f);

    // Row-pass tiling: row = 8 + (w&3) + 8*(w>>2) + 4*(lane>>4)
    const int  row = 8 + (w & 3) + ((w >> 2) << 3) + ((lane >> 4) << 2);
    const int  rp  = row - 16;
    const int  rp2 = rp * rp;
    const float fi = (float)(row - 8);
    const float fj = (float)((lane & 8) ? (lane & 7) : ((lane & 7) + 8));

    // Output mapping: k1_m = rbase' + perm[m], perm=[0,2,1,3]; r = k1^16.
    // k2(sc) = 2*brev4(sc&15) + (sc>>4); c = k2^16.
    const int rbase = ((__brev(l7) >> 27) ^ 16);  // 4-aligned
    const int c     = ((((__brev(sc & 15) >> 28)) << 1) + (sc >> 4)) ^ 16;

    const int b = blockIdx.x;

    float aP2 = 0.0f, aT2 = 0.0f, aPT = 0.0f, mQ = 0.0f, mT = 0.0f;

    for (int nb = 0; nb < NB; nb++) {
        const int batch = b * NB + nb;
        const float* op = output  + batch * (NS * 3);
        const float* tp = targets + batch * (NS * 3);

        // ---- fills ----
        if (tid < NS) {
            float sx = op[3 * tid + 0];
            float sy = op[3 * tid + 1];
            float z  = op[3 * tid + 2];
            sSeed[tid] = make_float4(-2.0f * sx, -2.0f * sy,
                                     fmaf(sx, sx, fmaf(sy, sy, 512.0f)), 0.0f);
            float s, cz;
            sincospif(2.0f * z, &s, &cz);
            sCS[tid] = make_float2(cz, s);
        }
        for (int t = tid; t < NS * 32; t += NT) {
            int s = t >> 5, x = t & 31;
            float tx  = tp[3 * s + 0];
            float ty  = tp[3 * s + 1];
            float amp = tp[3 * s + 2];
            float dx = (float)x - tx;
            float dy = (float)x - ty;
            sExT[x][s] = amp * __expf(dx * dx * (-1.0f / 4.5f));
            sEy[s][x]  = __expf(dy * dy * (-1.0f / 4.5f));
        }
        __syncthreads();

        // ---- single Voronoi argmin for this thread's ownable cell ----
        int best = 0x7fffffff;
        #pragma unroll
        for (int s = 0; s < NS; s++) {
            float4 S = sSeed[s];
            float val = fmaf(fi, S.x, fmaf(fj, S.y, S.z));
            best = min(best, (__float_as_int(val) & 0xffffffe0) | s);
        }
        const int L = best & 31;

        // ---- density for cells (row, colA) and (row, colA+16) ----
        float xAr, xAi, xBr, xBi;
        {
            int dA = colA - 16;
            bool inA = (rp2 + dA * dA <= 64);
            float2 csA = sCS[L];
            xAr = inA ? csA.x : 1.0f;
            xAi = inA ? csA.y : 0.0f;

            bool inB = (rp2 + colA * colA <= 64);
            int lblB = (colA <= 7) ? L : 0;
            float2 csB = sCS[lblB];
            xBr = inB ? csB.x : 1.0f;
            xBi = inB ? csB.y : 0.0f;
        }

        // ---- analytic row FFTs for rows 0..7 and 24..31 ----
        {
            float dc = (lane == 0) ? 32.0f : 0.0f;
            sG[w][lane] = make_float2(dc, 0.0f);          // rows 0..7
            if (w == 0) {
                float2 cs0 = sCS[0];
                float sg = (lane & 16) ? -1.0f : 1.0f;
                sG[24][lane] = make_float2(dc + (cs0.x - 1.0f) * sg, cs0.y * sg);
            } else {
                sG[24 + w][lane] = make_float2(dc, 0.0f); // rows 25..31
            }
        }

        // ---- ROW FFT: register stage h=16, then 4 shuffle stages ----
        float ar = xAr + xBr, ai = xAi + xBi;
        float tr = xAr - xBr, ti = xAi - xBi;
        float br = fmaf(tr, Wrow.x, -ti * Wrow.y);
        float bi = fmaf(tr, Wrow.y,  ti * Wrow.x);

        {   // h=8
            float sg = (lane & 8) ? -1.0f : 1.0f;
            float oar = __shfl_xor_sync(0xffffffffu, ar, 8);
            float oai = __shfl_xor_sync(0xffffffffu, ai, 8);
            float obr = __shfl_xor_sync(0xffffffffu, br, 8);
            float obi = __shfl_xor_sync(0xffffffffu, bi, 8);
            float uar = fmaf(sg, ar, oar), uai = fmaf(sg, ai, oai);
            float ubr = fmaf(sg, br, obr), ubi = fmaf(sg, bi, obi);
            ar = fmaf(uar, T8.x, -uai * T8.y); ai = fmaf(uar, T8.y, uai * T8.x);
            br = fmaf(ubr, T8.x, -ubi * T8.y); bi = fmaf(ubr, T8.y, ubi * T8.x);
        }
        {   // h=4
            float sg = (lane & 4) ? -1.0f : 1.0f;
            float oar = __shfl_xor_sync(0xffffffffu, ar, 4);
            float oai = __shfl_xor_sync(0xffffffffu, ai, 4);
            float obr = __shfl_xor_sync(0xffffffffu, br, 4);
            float obi = __shfl_xor_sync(0xffffffffu, bi, 4);
            float uar = fmaf(sg, ar, oar), uai = fmaf(sg, ai, oai);
            float ubr = fmaf(sg, br, obr), ubi = fmaf(sg, bi, obi);
            ar = fmaf(uar, T4r.x, -uai * T4r.y); ai = fmaf(uar, T4r.y, uai * T4r.x);
            br = fmaf(ubr, T4r.x, -ubi * T4r.y); bi = fmaf(ubr, T4r.y, ubi * T4r.x);
        }
        {   // h=2 swap trick
            float sg = (lane & 2) ? -1.0f : 1.0f;
            bool  sw = (lane & 3) == 3;
            float oar = __shfl_xor_sync(0xffffffffu, ar, 2);
            float oai = __shfl_xor_sync(0xffffffffu, ai, 2);
            float obr = __shfl_xor_sync(0xffffffffu, br, 2);
            float obi = __shfl_xor_sync(0xffffffffu, bi, 2);
            float uar = fmaf(sg, ar, oar), uai = fmaf(sg, ai, oai);
            float ubr = fmaf(sg, br, obr), ubi = fmaf(sg, bi, obi);
            ar = sw ?  uai : uar;  ai = sw ? -uar : uai;
            br = sw ?  ubi : ubr;  bi = sw ? -ubr : ubi;
        }
        {   // h=1 identity
            float sg = (lane & 1) ? -1.0f : 1.0f;
            float oar = __shfl_xor_sync(0xffffffffu, ar, 1);
            float oai = __shfl_xor_sync(0xffffffffu, ai, 1);
            float obr = __shfl_xor_sync(0xffffffffu, br, 1);
            float obi = __shfl_xor_sync(0xffffffffu, bi, 1);
            ar = fmaf(sg, ar, oar); ai = fmaf(sg, ai, oai);
            br = fmaf(sg, br, obr); bi = fmaf(sg, bi, obi);
        }

        // store: a -> col colA, b -> col colA+16 (STS.64, conflict-free per half)
        sG[row][colA]      = make_float2(ar, ai);
        sG[row][colA + 16] = make_float2(br, bi);
        __syncthreads();

        // ---- COLUMN FFT: 8 lanes/column, 4 points/thread ----
        float cr[4], ci[4];
        #pragma unroll
        for (int m = 0; m < 4; m++) {
            float2 v = sG[l7 + (m << 3)][sc];
            cr[m] = v.x; ci[m] = v.y;
        }
        {   // h=16 (register)
            float t0r = cr[0] - cr[2], t0i = ci[0] - ci[2];
            float t1r = cr[1] - cr[3], t1i = ci[1] - ci[3];
            cr[0] += cr[2]; ci[0] += ci[2];
            cr[1] += cr[3]; ci[1] += ci[3];
            cr[2] = fmaf(t0r, W1.x, -t0i * W1.y);
            ci[2] = fmaf(t0r, W1.y,  t0i * W1.x);
            float p1r = fmaf(t1r, W1.x, -t1i * W1.y);
            float p1i = fmaf(t1r, W1.y,  t1i * W1.x);
            cr[3] =  p1i;
            ci[3] = -p1r;
        }
        {   // h=8 (register)
            float t0r = cr[0] - cr[1], t0i = ci[0] - ci[1];
            cr[0] += cr[1]; ci[0] += ci[1];
            cr[1] = fmaf(t0r, W2.x, -t0i * W2.y);
            ci[1] = fmaf(t0r, W2.y,  t0i * W2.x);
            float t1r = cr[2] - cr[3], t1i = ci[2] - ci[3];
            cr[2] += cr[3]; ci[2] += ci[3];
            cr[3] = fmaf(t1r, W2.x, -t1i * W2.y);
            ci[3] = fmaf(t1r, W2.y,  t1i * W2.x);
        }
        {   // h=4 (shuffle)
            float sg = (lane & 4) ? -1.0f : 1.0f;
            #pragma unroll
            for (int m = 0; m < 4; m++) {
                float o_r = __shfl_xor_sync(0xffffffffu, cr[m], 4);
                float o_i = __shfl_xor_sync(0xffffffffu, ci[m], 4);
                float ur = fmaf(sg, cr[m], o_r);
                float ui = fmaf(sg, ci[m], o_i);
                cr[m] = fmaf(ur, W4.x, -ui * W4.y);
                ci[m] = fmaf(ur, W4.y,  ui * W4.x);
            }
        }
        {   // h=2 swap trick
            float sg = (lane & 2) ? -1.0f : 1.0f;
            bool  sw = (lane & 3) == 3;
            #pragma unroll
            for (int m = 0; m < 4; m++) {
                float o_r = __shfl_xor_sync(0xffffffffu, cr[m], 2);
                float o_i = __shfl_xor_sync(0xffffffffu, ci[m], 2);
                float ur = fmaf(sg, cr[m], o_r);
                float ui = fmaf(sg, ci[m], o_i);
                cr[m] = sw ?  ui : ur;
                ci[m] = sw ? -ur : ui;
            }
        }
        {   // h=1 identity
            float sg = (lane & 1) ? -1.0f : 1.0f;
            #pragma unroll
            for (int m = 0; m < 4; m++) {
                float o_r = __shfl_xor_sync(0xffffffffu, cr[m], 1);
                float o_i = __shfl_xor_sync(0xffffffffu, ci[m], 1);
                cr[m] = fmaf(sg, cr[m], o_r);
                ci[m] = fmaf(sg, ci[m], o_i);
            }
        }

        // ---- magnitude + target + accumulate ----
        {
            float Q[4], P[4], T[4];
            #pragma unroll
            for (int m = 0; m < 4; m++) {
                Q[m] = fmaf(cr[m], cr[m], ci[m] * ci[m]);
                P[m] = sqrtf(Q[m]);
                T[m] = 0.0f;
            }
            const float* exRow = &sExT[c][0];
            #pragma unroll
            for (int s2 = 0; s2 < NS / 2; s2++) {
                float2 ex2 = *reinterpret_cast<const float2*>(&exRow[2 * s2]);
                float4 E0  = *reinterpret_cast<const float4*>(&sEy[2 * s2][rbase]);
                float4 E1  = *reinterpret_cast<const float4*>(&sEy[2 * s2 + 1][rbase]);
                T[0] = fmaf(ex2.x, E0.x, fmaf(ex2.y, E1.x, T[0]));   // r offset 0
                T[1] = fmaf(ex2.x, E0.z, fmaf(ex2.y, E1.z, T[1]));   // r offset 2
                T[2] = fmaf(ex2.x, E0.y, fmaf(ex2.y, E1.y, T[2]));   // r offset 1
                T[3] = fmaf(ex2.x, E0.w, fmaf(ex2.y, E1.w, T[3]));   // r offset 3
            }
            #pragma unroll
            for (int m = 0; m < 4; m++) {
                aP2 += Q[m];
                aT2 = fmaf(T[m], T[m], aT2);
                aPT = fmaf(P[m], T[m], aPT);
                mQ = fmaxf(mQ, Q[m]);
                mT = fmaxf(mT, T[m]);
            }
        }
        __syncthreads();   // before next batch overwrites smem
    }

    // ---- block reduction (once per NB batches) ----
    unsigned ruQ = __reduce_max_sync(0xffffffffu, (unsigned)__float_as_int(mQ));
    unsigned ruT = __reduce_max_sync(0xffffffffu, (unsigned)__float_as_int(mT));
    #pragma unroll
    for (int off = 16; off; off >>= 1) {
        aP2 += __shfl_down_sync(0xffffffffu, aP2, off);
        aT2 += __shfl_down_sync(0xffffffffu, aT2, off);
        aPT += __shfl_down_sync(0xffffffffu, aPT, off);
    }
    __shared__ int redI[16];
    if (lane == 0) {
        redD[w]      = (double)aP2;
        redD[8 + w]  = (double)aT2;
        redD[16 + w] = (double)aPT;
        redI[w]      = (int)ruQ;
        redI[8 + w]  = (int)ruT;
    }
    __syncthreads();
    if (tid == 0) {
        double bP2 = 0.0, bT2 = 0.0, bPT = 0.0;
        int    bMQ = 0, bMT = 0;
        #pragma unroll
        for (int i = 0; i < 8; i++) {
            bP2 += redD[i];
            bT2 += redD[8 + i];
            bPT += redD[16 + i];
            bMQ = max(bMQ, redI[i]);
            bMT = max(bMT, redI[8 + i]);
        }
        atomicAdd(&g_sumP2, bP2);
        atomicAdd(&g_sumT2, bT2);
        atomicAdd(&g_sumPT, bPT);
        atomicMax(&g_maxQ, bMQ);
        atomicMax(&g_maxT, bMT);

        __threadfence();
        unsigned prev = atomicAdd(&g_count, 1u);
        if (prev == gridDim.x - 1u) {
            __threadfence();
            double SP2 = g_sumP2;
            double ST2 = g_sumT2;
            double SPT = g_sumPT;
            double Mp = sqrt((double)__int_as_float(g_maxQ));
            double Mt = (double)__int_as_float(g_maxT);
            double num = SP2 / (Mp * Mp) - 2.0 * SPT / (Mp * Mt) + ST2 / (Mt * Mt);
            out[0] = (float)(num * (Mp * Mt) / sqrt(SP2 * ST2));
            // self-reset for next graph replay (matches static init state)
            g_sumP2 = 0.0;
            g_sumT2 = 0.0;
            g_sumPT = 0.0;
            g_maxQ  = 0;
            g_maxT  = 0;
            g_count = 0u;
        }
    }
}

extern "C" void kernel_launch(void* const* d_in, const int* in_sizes, int n_in,
                              void* d_out, int out_size)
{
    const float* output  = (const float*)d_in[0];
    const float* targets = (const float*)d_in[1];
    int B = in_sizes[0] / (NS * 3);

    loss_main<<<B / NB, NT>>>(output, targets, (float*)d_out);
}